// round 9
// baseline (speedup 1.0000x reference)
#include <cuda_runtime.h>
#include <cstdint>

// Problem shape (fixed by the dataset instance)
#define NBATCH 32
#define EDIM   512
#define TDIM   512
#define M_ROWS 16384           // NBATCH*TDIM
#define NE     8192            // number of codes
#define NET    8388608         // NBATCH*EDIM*TDIM

typedef unsigned long long ull;

// ---- scratch (__device__ globals; no allocations allowed) ----
__device__ float  g_zz[M_ROWS];
__device__ float  g_see[NE];
__device__ float  g_pval[2 * M_ROWS];
__device__ int    g_pidx[2 * M_ROWS];
__device__ int    g_idx[M_ROWS];
__device__ int    g_counts[NE];
__device__ double g_loss;

// packed f32x2 FMA: two independent IEEE-rn fp32 FMAs in one instr (FFMA2).
// Per-lane bitwise identical to scalar __fmaf_rn -> accumulation chain frozen.
__device__ __forceinline__ void fma2(ull& acc, ull a, ull b) {
    asm("fma.rn.f32x2 %0, %1, %2, %0;" : "+l"(acc) : "l"(a), "l"(b));
}
__device__ __forceinline__ ull pack2(float lo, float hi) {
    ull r;
    asm("mov.b64 %0, {%1, %2};" : "=l"(r) : "f"(lo), "f"(hi));
    return r;
}
__device__ __forceinline__ void unpack2(ull v, float& lo, float& hi) {
    asm("mov.b64 {%0, %1}, %2;" : "=f"(lo), "=f"(hi) : "l"(v));
}

// ============================================================
// Row sum-of-squares (zz / see). zz shifts every d_j of a row
// uniformly (argmin-invariant); see perturbations ~6e-11 << d-bucket.
// ============================================================
__device__ __forceinline__ float row_sumsq(float x0, float x1,
                                           float* ws, int tid) {
    float v = __fadd_rn(__fmul_rn(x0, x0), __fmul_rn(x1, x1));
    #pragma unroll
    for (int o = 16; o >= 1; o >>= 1)
        v = __fadd_rn(v, __shfl_down_sync(0xffffffffu, v, o));
    if ((tid & 31) == 0) ws[tid >> 5] = v;
    __syncthreads();
    float r = 0.f;
    if (tid < 32) {
        float p = (tid < 8) ? ws[tid] : 0.f;
        #pragma unroll
        for (int o = 16; o >= 1; o >>= 1)
            p = __fadd_rn(p, __shfl_down_sync(0xffffffffu, p, o));
        r = p;
    }
    return r;
}

__global__ void see_kernel(const float* __restrict__ emb) {
    __shared__ float ws[8];
    const int j = blockIdx.x, tid = threadIdx.x;
    float2 x = *(const float2*)(emb + (size_t)j * EDIM + 2 * tid);
    float r = row_sumsq(x.x, x.y, ws, tid);
    if (tid == 0) {
        g_see[j]    = r;
        g_counts[j] = 0;
        if (j == 0) g_loss = 0.0;
    }
}

__global__ void zz_kernel(const float* __restrict__ z) {
    __shared__ float ws[8];
    const int m = blockIdx.x, tid = threadIdx.x;
    const int n = m >> 9, t = m & 511;
    const float* base = z + (size_t)n * (EDIM * TDIM) + t;
    float x0 = base[(size_t)(2 * tid)     * TDIM];
    float x1 = base[(size_t)(2 * tid + 1) * TDIM];
    float r = row_sumsq(x0, x1, ws, tid);
    if (tid == 0) g_zz[m] = r;
}

// ============================================================
// Kernel 2: FULL-FP32 GEMM via packed FFMA2 (2x the scalar-FFMA
// issue roofline; per-lane bitwise == scalar chain, K ascending,
// one accumulator per element). Epilogue = reference's exact tree:
//   d = fl( fl(zz + see) - fl(g + g) )
// 128x128 block tile, BK=32, 8x8 microtile as 8x(4 x f32x2) pairs.
// grid = (2 code halves, 128 row tiles), 256 thr, 2 blocks/SM.
// ============================================================
#define BM 128
#define BN 128
#define BK 32
#define NTILES_J 32   // 4096 codes per half / 128
#define NCHUNK_K 16   // 512 / 32

__global__ __launch_bounds__(256, 2)
void vq_argmin_kernel(const float* __restrict__ z,
                      const float* __restrict__ emb) {
    __shared__ float As[BK][BM];   // [k][m]
    __shared__ float Bs[BK][BN];   // [k][j]

    const int tid = threadIdx.x;
    const int h   = blockIdx.x;          // code half 0/1
    const int rt  = blockIdx.y;          // row tile 0..127
    const int m0  = rt * BM;
    const int n   = m0 >> 9;
    const int t0  = m0 & 511;
    const float* zbase = z + ((size_t)n * EDIM * TDIM) + t0;

    const int warpId = tid >> 5, lane = tid & 31;
    const int wy = warpId >> 1, wx = warpId & 1;
    const int wr = lane >> 3,   wc = lane & 7;
    const int rowb = wy * 32 + wr * 8;   // first local row
    const int colb = wx * 64 + wc * 8;   // first local code

    float bestv[8];
    int   besti[8];
    #pragma unroll
    for (int i = 0; i < 8; i++) { bestv[i] = 3.4e38f; besti[i] = 0x7fffffff; }

    const int jhalf0 = h * (NE / 2);

    for (int jt = 0; jt < NTILES_J; ++jt) {
        const int j0 = jhalf0 + jt * BN;
        // acc2[i][p] = (acc[i][2p], acc[i][2p+1]) packed f32x2
        ull acc2[8][4];
        #pragma unroll
        for (int i = 0; i < 8; i++)
            #pragma unroll
            for (int p = 0; p < 4; p++) acc2[i][p] = 0ull;

        for (int kt = 0; kt < NCHUNK_K; ++kt) {     // K ascending
            const int e0 = kt * BK;
            // stage z chunk: 32 k-rows x 128 contiguous floats
            #pragma unroll
            for (int it = 0; it < 4; ++it) {
                int id = tid + it * 256;            // 0..1023
                int k  = id >> 5;                   // 0..31
                int f4 = id & 31;
                float4 v = *(const float4*)(zbase + (size_t)(e0 + k) * TDIM + f4 * 4);
                *(float4*)(&As[k][f4 * 4]) = v;
            }
            // stage emb chunk: 128 code rows x 32 e's, transpose to [k][j]
            #pragma unroll
            for (int it = 0; it < 4; ++it) {
                int id = tid + it * 256;
                int j  = id >> 3;                   // 0..127
                int q4 = id & 7;                    // 0..7
                float4 v = *(const float4*)(emb + (size_t)(j0 + j) * EDIM + e0 + q4 * 4);
                Bs[q4 * 4 + 0][j] = v.x;
                Bs[q4 * 4 + 1][j] = v.y;
                Bs[q4 * 4 + 2][j] = v.z;
                Bs[q4 * 4 + 3][j] = v.w;
            }
            __syncthreads();
            #pragma unroll 8
            for (int kk = 0; kk < BK; ++kk) {
                float a[8];
                *(float4*)&a[0] = *(const float4*)&As[kk][rowb];
                *(float4*)&a[4] = *(const float4*)&As[kk][rowb + 4];
                // b pairs: adjacent columns -> direct 64-bit lanes
                ulonglong2 bp0 = *(const ulonglong2*)&Bs[kk][colb];
                ulonglong2 bp1 = *(const ulonglong2*)&Bs[kk][colb + 4];
                ull b2[4] = { bp0.x, bp0.y, bp1.x, bp1.y };
                #pragma unroll
                for (int i = 0; i < 8; i++) {
                    ull a2 = pack2(a[i], a[i]);     // replicate row operand
                    #pragma unroll
                    for (int p = 0; p < 4; p++)
                        fma2(acc2[i][p], a2, b2[p]);
                }
            }
            __syncthreads();
        }
        // Reference epilogue: d = fl( fl(zz+see) - fl(2g) ).
        // j ascends within each slot -> strict < keeps lowest index.
        #pragma unroll
        for (int p = 0; p < 4; p++) {
            int j = j0 + colb + 2 * p;
            float s0 = __ldg(&g_see[j]);
            float s1 = __ldg(&g_see[j + 1]);
            #pragma unroll
            for (int i = 0; i < 8; i++) {
                float zz = __ldg(&g_zz[m0 + rowb + i]);
                float g0, g1;
                unpack2(acc2[i][p], g0, g1);
                float d0 = __fsub_rn(__fadd_rn(zz, s0), __fadd_rn(g0, g0));
                float d1 = __fsub_rn(__fadd_rn(zz, s1), __fadd_rn(g1, g1));
                if (d0 < bestv[i]) { bestv[i] = d0; besti[i] = j; }
                if (d1 < bestv[i]) { bestv[i] = d1; besti[i] = j + 1; }
            }
        }
    }

    // cross-thread reduction: 16 threads share each row octet
    __syncthreads();
    float* rv = &As[0][0];             // 2048 floats
    int*   ri = (int*)&Bs[0][0];       // 2048 ints
    const int tcol = wx * 8 + wc;      // 0..15
    #pragma unroll
    for (int i = 0; i < 8; i++) {
        int rowl = rowb + i;
        rv[rowl * 16 + tcol] = bestv[i];
        ri[rowl * 16 + tcol] = besti[i];
    }
    __syncthreads();
    if (tid < BM) {
        float bv = rv[tid * 16];
        int   bi = ri[tid * 16];
        #pragma unroll
        for (int q = 1; q < 16; q++) {
            float v  = rv[tid * 16 + q];
            int   ix = ri[tid * 16 + q];
            if (v < bv || (v == bv && ix < bi)) { bv = v; bi = ix; }
        }
        g_pval[h * M_ROWS + m0 + tid] = bv;
        g_pidx[h * M_ROWS + m0 + tid] = bi;
    }
}

// ============================================================
// Kernel 3: merge halves + histogram (half0 indices < half1 ->
// tie keeps half0 = lowest index, matching argmin)
// ============================================================
__global__ void merge_kernel() {
    int m = blockIdx.x * blockDim.x + threadIdx.x;
    if (m >= M_ROWS) return;
    float v0 = g_pval[m];          int i0 = g_pidx[m];
    float v1 = g_pval[M_ROWS + m]; int i1 = g_pidx[M_ROWS + m];
    int idx = (v1 < v0) ? i1 : i0;
    g_idx[m] = idx;
    atomicAdd(&g_counts[idx], 1);
}

// ============================================================
// Kernel 4: straight-through output (reference's exact two rounding
// ops -> bitwise output with matching idx) + fp64 loss accumulation
// ============================================================
__global__ void output_loss_kernel(const float* __restrict__ z,
                                   const float* __restrict__ emb,
                                   float* __restrict__ out) {
    int g = blockIdx.x * blockDim.x + threadIdx.x;   // < NET exactly
    int t = g & (TDIM - 1);
    int e = (g >> 9) & (EDIM - 1);
    int n = g >> 18;
    int m = n * TDIM + t;
    int j = g_idx[m];
    float zf = z[g];
    float zq = __ldg(emb + (size_t)j * EDIM + e);
    float dsub = __fsub_rn(zq, zf);      // fl(z_q - zf)
    out[g] = __fadd_rn(zf, dsub);        // fl(zf + fl(z_q - zf))
    float sq = __fmul_rn(dsub, dsub);

    __shared__ float red[256];
    red[threadIdx.x] = sq;
    __syncthreads();
    #pragma unroll
    for (int s = 128; s > 0; s >>= 1) {
        if (threadIdx.x < s) red[threadIdx.x] += red[threadIdx.x + s];
        __syncthreads();
    }
    if (threadIdx.x == 0) atomicAdd(&g_loss, (double)red[0]);
}

// ============================================================
// Kernel 5: perplexity + scalars
// ============================================================
__global__ void scalar_kernel(float* __restrict__ out) {
    __shared__ double red[256];
    double s = 0.0;
    for (int j = threadIdx.x; j < NE; j += 256) {
        float em   = (float)g_counts[j] / (float)M_ROWS;
        float term = em * logf(em + 1e-10f);
        s += (double)term;
    }
    red[threadIdx.x] = s;
    __syncthreads();
    #pragma unroll
    for (int st = 128; st > 0; st >>= 1) {
        if (threadIdx.x < st) red[threadIdx.x] += red[threadIdx.x + st];
        __syncthreads();
    }
    if (threadIdx.x == 0) {
        double mean = g_loss / (double)((size_t)M_ROWS * EDIM);
        out[NET]     = (float)(1.25 * mean);       // (1 + BETA) * mean
        out[NET + 1] = expf((float)(-red[0]));     // perplexity
    }
}

// ============================================================
extern "C" void kernel_launch(void* const* d_in, const int* in_sizes, int n_in,
                              void* d_out, int out_size) {
    (void)in_sizes; (void)n_in; (void)out_size;
    const float* z   = (const float*)d_in[0];   // [N, E, T] fp32
    const float* emb = (const float*)d_in[1];   // [n_e, E] fp32
    float* out = (float*)d_out;

    see_kernel<<<NE, 256>>>(emb);
    zz_kernel<<<M_ROWS, 256>>>(z);

    dim3 g2(2, 128);
    vq_argmin_kernel<<<g2, 256>>>(z, emb);

    merge_kernel<<<M_ROWS / 256, 256>>>();

    output_loss_kernel<<<NET / 256, 256>>>(z, emb, out);

    scalar_kernel<<<1, 256>>>(out);
}

// round 10
// speedup vs baseline: 1.5461x; 1.5461x over previous
#include <cuda_runtime.h>
#include <cstdint>

// Problem shape (fixed by the dataset instance)
#define NBATCH 32
#define EDIM   512
#define TDIM   512
#define M_ROWS 16384           // NBATCH*TDIM
#define NE     8192            // number of codes
#define NET    8388608         // NBATCH*EDIM*TDIM

#define CAP    32              // candidate cap per row (warp-sized)
#define MARGIN 2e-3f           // ~33 d-ulps; bound on 2*|d_hat - d_ref| is ~5e-4

// ---- scratch (__device__ globals; no allocations allowed) ----
__device__ float  g_zz[M_ROWS];
__device__ float  g_see[NE];
__device__ float  g_pval[2 * M_ROWS];   // per-half min of d_hat
__device__ float  g_dthr[M_ROWS];       // min + margin
__device__ int    g_ccnt[M_ROWS];       // candidate counts
__device__ int    g_cand[M_ROWS * CAP]; // candidate indices
__device__ int    g_idx[M_ROWS];
__device__ int    g_counts[NE];
__device__ double g_loss;

// TF32 rounding (approximation pass only — any rounding works)
__device__ __forceinline__ float tf32r(float x) {
    uint32_t u;
    asm("cvt.rna.tf32.f32 %0, %1;" : "=r"(u) : "f"(x));
    return __uint_as_float(u);
}

// m16n8k8 TF32 tensor-core MMA, fp32 accumulate
__device__ __forceinline__ void mma_tf32(float* c,
                                         const uint32_t* a,
                                         const uint32_t* b) {
    asm volatile(
        "mma.sync.aligned.m16n8k8.row.col.f32.tf32.tf32.f32 "
        "{%0,%1,%2,%3}, {%4,%5,%6,%7}, {%8,%9}, {%0,%1,%2,%3};"
        : "+f"(c[0]), "+f"(c[1]), "+f"(c[2]), "+f"(c[3])
        : "r"(a[0]), "r"(a[1]), "r"(a[2]), "r"(a[3]),
          "r"(b[0]), "r"(b[1]));
}

// ============================================================
// Row sum-of-squares (zz / see). Not bit-critical (zz shifts a row's
// d uniformly; see error ~6e-11 << margin), just accurate.
// ============================================================
__device__ __forceinline__ float row_sumsq(float x0, float x1,
                                           float* ws, int tid) {
    float v = __fadd_rn(__fmul_rn(x0, x0), __fmul_rn(x1, x1));
    #pragma unroll
    for (int o = 16; o >= 1; o >>= 1)
        v = __fadd_rn(v, __shfl_down_sync(0xffffffffu, v, o));
    if ((tid & 31) == 0) ws[tid >> 5] = v;
    __syncthreads();
    float r = 0.f;
    if (tid < 32) {
        float p = (tid < 8) ? ws[tid] : 0.f;
        #pragma unroll
        for (int o = 16; o >= 1; o >>= 1)
            p = __fadd_rn(p, __shfl_down_sync(0xffffffffu, p, o));
        r = p;
    }
    return r;
}

__global__ void see_kernel(const float* __restrict__ emb) {
    __shared__ float ws[8];
    const int j = blockIdx.x, tid = threadIdx.x;
    float2 x = *(const float2*)(emb + (size_t)j * EDIM + 2 * tid);
    float r = row_sumsq(x.x, x.y, ws, tid);
    if (tid == 0) {
        g_see[j]    = r;
        g_counts[j] = 0;
    }
}

__global__ void zz_kernel(const float* __restrict__ z) {
    __shared__ float ws[8];
    const int m = blockIdx.x, tid = threadIdx.x;
    const int n = m >> 9, t = m & 511;
    const float* base = z + (size_t)n * (EDIM * TDIM) + t;
    float x0 = base[(size_t)(2 * tid)     * TDIM];
    float x1 = base[(size_t)(2 * tid + 1) * TDIM];
    float r = row_sumsq(x0, x1, ws, tid);
    if (tid == 0) {
        g_zz[m]   = r;
        g_ccnt[m] = 0;
    }
}

// tiny init kernel (also shifts launch order so ncu -s 5 captures sweep B)
__global__ void init_kernel() {
    if (threadIdx.x == 0) g_loss = 0.0;
}

// ============================================================
// Kernel AB: TF32 tensor GEMM sweep (R5 body — numerically validated).
//   d_hat = fl( see[j] - fl(acc+acc) )    (zz omitted: row-constant)
// mode 0: per-row min of d_hat -> g_pval[half*M + m]
// mode 1: collect candidates with d_hat <= g_dthr[m]
// Both modes share one compiled GEMM+d_hat path -> bitwise-identical
// d_hat across sweeps (soundness of the threshold test).
// Block tile 128x128, BK=32, 8 warps (4M x 2N), warp 32x64.
// grid = (2 code halves, 128 row tiles)
// ============================================================
#define BK 32
#define AS_STRIDE 136
#define BS_STRIDE 36

__global__ __launch_bounds__(256)
void sweep_kernel(const float* __restrict__ z,
                  const float* __restrict__ emb,
                  int mode) {
    __shared__ float As[BK][AS_STRIDE];    // [k][m], tf32-rounded z
    __shared__ float Bs[128][BS_STRIDE];   // [j][k], tf32-rounded emb

    const int tid = threadIdx.x;
    const int h   = blockIdx.x;            // code half 0/1
    const int m0  = blockIdx.y * 128;      // row tile base
    const int nb  = m0 >> 9, t0 = m0 & 511;
    const float* zbase = z + (size_t)nb * EDIM * TDIM + t0;

    const int warpId = tid >> 5, lane = tid & 31;
    const int warpRow = warpId >> 1, warpCol = warpId & 1;
    const int wm = warpRow * 32, wn = warpCol * 64;
    const int r  = lane >> 2,  tg = lane & 3;

    // thresholds for this thread's 4 C-rows (mode 1)
    float thr[4];
    #pragma unroll
    for (int i = 0; i < 4; i++) {
        int row = m0 + wm + (i >> 1) * 16 + (i & 1) * 8 + r;
        thr[i] = (mode == 1) ? __ldg(&g_dthr[row]) : 0.f;
    }

    float bestv[4];
    #pragma unroll
    for (int i = 0; i < 4; i++) bestv[i] = 3.4e38f;

    const int jh0 = h * (NE / 2);

    for (int jt = 0; jt < 32; ++jt) {
        const int j0 = jh0 + jt * 128;
        float acc[2][8][4];
        #pragma unroll
        for (int am = 0; am < 2; am++)
            #pragma unroll
            for (int an = 0; an < 8; an++)
                #pragma unroll
                for (int q = 0; q < 4; q++) acc[am][an][q] = 0.f;

        for (int kt = 0; kt < 16; ++kt) {
            const int e0 = kt * BK;
            #pragma unroll
            for (int it = 0; it < 4; ++it) {
                int id = tid + it * 256;
                int k  = id >> 5, f4 = id & 31;
                float4 v = *(const float4*)(zbase + (size_t)(e0 + k) * TDIM + f4 * 4);
                v.x = tf32r(v.x); v.y = tf32r(v.y);
                v.z = tf32r(v.z); v.w = tf32r(v.w);
                *(float4*)&As[k][f4 * 4] = v;
            }
            #pragma unroll
            for (int it = 0; it < 4; ++it) {
                int id = tid + it * 256;
                int j  = id >> 3, q4 = id & 7;
                float4 v = *(const float4*)(emb + (size_t)(j0 + j) * EDIM + e0 + q4 * 4);
                v.x = tf32r(v.x); v.y = tf32r(v.y);
                v.z = tf32r(v.z); v.w = tf32r(v.w);
                *(float4*)&Bs[j][q4 * 4] = v;
            }
            __syncthreads();

            #pragma unroll
            for (int ks = 0; ks < 4; ++ks) {
                const int k8 = ks * 8;
                uint32_t a[2][4], b[8][2];
                #pragma unroll
                for (int am = 0; am < 2; ++am) {
                    int mb = wm + am * 16 + r;
                    a[am][0] = __float_as_uint(As[k8 + tg    ][mb]);
                    a[am][1] = __float_as_uint(As[k8 + tg    ][mb + 8]);
                    a[am][2] = __float_as_uint(As[k8 + tg + 4][mb]);
                    a[am][3] = __float_as_uint(As[k8 + tg + 4][mb + 8]);
                }
                #pragma unroll
                for (int an = 0; an < 8; ++an) {
                    int nf = wn + an * 8 + r;
                    b[an][0] = __float_as_uint(Bs[nf][k8 + tg]);
                    b[an][1] = __float_as_uint(Bs[nf][k8 + tg + 4]);
                }
                #pragma unroll
                for (int am = 0; am < 2; ++am)
                    #pragma unroll
                    for (int an = 0; an < 8; ++an)
                        mma_tf32(acc[am][an], a[am], b[an]);
            }
            __syncthreads();
        }

        // d_hat epilogue (identical instruction sequence in both modes)
        #pragma unroll
        for (int an = 0; an < 8; ++an) {
            int nloc = wn + an * 8 + tg * 2;
            int j = j0 + nloc;
            float s0 = __ldg(&g_see[j]);
            float s1 = __ldg(&g_see[j + 1]);
            #pragma unroll
            for (int am = 0; am < 2; ++am) {
                #pragma unroll
                for (int half = 0; half < 2; ++half) {
                    int bi = am * 2 + half;
                    float g0 = acc[am][an][half * 2 + 0];
                    float g1 = acc[am][an][half * 2 + 1];
                    float d0 = __fsub_rn(s0, __fadd_rn(g0, g0));
                    float d1 = __fsub_rn(s1, __fadd_rn(g1, g1));
                    if (mode == 0) {
                        bestv[bi] = fminf(bestv[bi], fminf(d0, d1));
                    } else {
                        int row = m0 + wm + am * 16 + half * 8 + r;
                        if (d0 <= thr[bi]) {
                            int pos = atomicAdd(&g_ccnt[row], 1);
                            if (pos < CAP) g_cand[row * CAP + pos] = j;
                        }
                        if (d1 <= thr[bi]) {
                            int pos = atomicAdd(&g_ccnt[row], 1);
                            if (pos < CAP) g_cand[row * CAP + pos] = j + 1;
                        }
                    }
                }
            }
        }
    }

    if (mode == 0) {
        // cross-thread min: 8 threads own each of the 128 rows
        __syncthreads();
        float* rv = &As[0][0];
        const int slot = warpCol * 4 + tg;
        #pragma unroll
        for (int i = 0; i < 4; i++) {
            int row = wm + (i >> 1) * 16 + (i & 1) * 8 + r;
            rv[row * 8 + slot] = bestv[i];
        }
        __syncthreads();
        if (tid < 128) {
            float bv = rv[tid * 8];
            #pragma unroll
            for (int q = 1; q < 8; q++) bv = fminf(bv, rv[tid * 8 + q]);
            g_pval[h * M_ROWS + m0 + tid] = bv;
        }
    }
}

// ============================================================
// Merge per-half mins into per-row threshold
// ============================================================
__global__ void mergemin_kernel() {
    int m = blockIdx.x * blockDim.x + threadIdx.x;
    if (m < M_ROWS)
        g_dthr[m] = fminf(g_pval[m], g_pval[M_ROWS + m]) + MARGIN;
}

// ============================================================
// Kernel C: exact resolution. One warp per row. Each candidate gets
// the reference-exact serial ascending-K fp32 FMA chain and epilogue
//   d = fl( fl(zz+see) - fl(g+g) )
// then lexicographic (d, idx) min -> argmin with lowest-index ties.
// Fallback (cnt > CAP, ~never): exact full scan of all 8192 codes.
// ============================================================
__global__ void resolve_kernel(const float* __restrict__ z,
                               const float* __restrict__ emb) {
    const int tid = threadIdx.x;
    const int lane = tid & 31;
    const int m = blockIdx.x * 8 + (tid >> 5);
    const int n = m >> 9, t = m & 511;
    const float* zrow = z + (size_t)n * (EDIM * TDIM) + t;
    const float zz = __ldg(&g_zz[m]);
    const int cnt = g_ccnt[m];

    float bv = 3.4e38f;
    int   bi = 0x7fffffff;

    if (cnt <= CAP) {
        if (lane < cnt) {
            int j = g_cand[m * CAP + lane];
            const float* e = emb + (size_t)j * EDIM;
            float acc = 0.f;
            #pragma unroll 8
            for (int k = 0; k < EDIM; ++k)
                acc = __fmaf_rn(zrow[(size_t)k * TDIM], __ldg(&e[k]), acc);
            bv = __fsub_rn(__fadd_rn(zz, __ldg(&g_see[j])),
                           __fadd_rn(acc, acc));
            bi = j;
        }
    } else {
        // sound fallback: exact scan of every code
        for (int j = lane; j < NE; j += 32) {
            const float* e = emb + (size_t)j * EDIM;
            float acc = 0.f;
            #pragma unroll 8
            for (int k = 0; k < EDIM; ++k)
                acc = __fmaf_rn(zrow[(size_t)k * TDIM], __ldg(&e[k]), acc);
            float d = __fsub_rn(__fadd_rn(zz, __ldg(&g_see[j])),
                                __fadd_rn(acc, acc));
            if (d < bv || (d == bv && j < bi)) { bv = d; bi = j; }
        }
    }

    // warp lexicographic min (value, then lowest index)
    #pragma unroll
    for (int o = 16; o >= 1; o >>= 1) {
        float ov = __shfl_down_sync(0xffffffffu, bv, o);
        int   oi = __shfl_down_sync(0xffffffffu, bi, o);
        if (ov < bv || (ov == bv && oi < bi)) { bv = ov; bi = oi; }
    }
    if (lane == 0) {
        g_idx[m] = bi;
        atomicAdd(&g_counts[bi], 1);
    }
}

// ============================================================
// Kernel: straight-through output (reference's exact two rounding
// ops -> bitwise output with matching idx) + fp64 loss accumulation
// ============================================================
__global__ void output_loss_kernel(const float* __restrict__ z,
                                   const float* __restrict__ emb,
                                   float* __restrict__ out) {
    int g = blockIdx.x * blockDim.x + threadIdx.x;   // < NET exactly
    int t = g & (TDIM - 1);
    int e = (g >> 9) & (EDIM - 1);
    int n = g >> 18;
    int m = n * TDIM + t;
    int j = g_idx[m];
    float zf = z[g];
    float zq = __ldg(emb + (size_t)j * EDIM + e);
    float dsub = __fsub_rn(zq, zf);      // fl(z_q - zf)
    out[g] = __fadd_rn(zf, dsub);        // fl(zf + fl(z_q - zf))
    float sq = __fmul_rn(dsub, dsub);

    __shared__ float red[256];
    red[threadIdx.x] = sq;
    __syncthreads();
    #pragma unroll
    for (int s = 128; s > 0; s >>= 1) {
        if (threadIdx.x < s) red[threadIdx.x] += red[threadIdx.x + s];
        __syncthreads();
    }
    if (threadIdx.x == 0) atomicAdd(&g_loss, (double)red[0]);
}

// ============================================================
// Kernel: perplexity + scalars
// ============================================================
__global__ void scalar_kernel(float* __restrict__ out) {
    __shared__ double red[256];
    double s = 0.0;
    for (int j = threadIdx.x; j < NE; j += 256) {
        float em   = (float)g_counts[j] / (float)M_ROWS;
        float term = em * logf(em + 1e-10f);
        s += (double)term;
    }
    red[threadIdx.x] = s;
    __syncthreads();
    #pragma unroll
    for (int st = 128; st > 0; st >>= 1) {
        if (threadIdx.x < st) red[threadIdx.x] += red[threadIdx.x + st];
        __syncthreads();
    }
    if (threadIdx.x == 0) {
        double mean = g_loss / (double)((size_t)M_ROWS * EDIM);
        out[NET]     = (float)(1.25 * mean);       // (1 + BETA) * mean
        out[NET + 1] = expf((float)(-red[0]));     // perplexity
    }
}

// ============================================================
extern "C" void kernel_launch(void* const* d_in, const int* in_sizes, int n_in,
                              void* d_out, int out_size) {
    (void)in_sizes; (void)n_in; (void)out_size;
    const float* z   = (const float*)d_in[0];   // [N, E, T] fp32
    const float* emb = (const float*)d_in[1];   // [n_e, E] fp32
    float* out = (float*)d_out;

    see_kernel<<<NE, 256>>>(emb);               // 1
    zz_kernel<<<M_ROWS, 256>>>(z);              // 2
    init_kernel<<<1, 32>>>();                   // 3

    dim3 g2(2, 128);
    sweep_kernel<<<g2, 256>>>(z, emb, 0);       // 4: min sweep
    mergemin_kernel<<<64, 256>>>();             // 5
    sweep_kernel<<<g2, 256>>>(z, emb, 1);       // 6: candidate sweep (ncu slot)

    resolve_kernel<<<M_ROWS / 8, 256>>>(z, emb);        // 7
    output_loss_kernel<<<NET / 256, 256>>>(z, emb, out); // 8
    scalar_kernel<<<1, 256>>>(out);             // 9
}

// round 11
// speedup vs baseline: 2.5459x; 1.6467x over previous
#include <cuda_runtime.h>
#include <cuda_fp16.h>
#include <cstdint>

// Problem shape (fixed by the dataset instance)
#define NBATCH 32
#define EDIM   512
#define TDIM   512
#define M_ROWS 16384           // NBATCH*TDIM
#define NE     8192            // number of codes
#define NET    8388608         // NBATCH*EDIM*TDIM

#define CAP    32              // candidate cap per row (warp-sized)
#define MARGIN 2e-3f           // >= 2*(tf32 err) + fp16 q + bucket; validated R10

// ---- scratch (__device__ globals; no allocations allowed) ----
__device__ float  g_zz[M_ROWS];
__device__ float  g_see[NE];
__device__ __half g_dhat[(size_t)M_ROWS * NE];  // 268MB approx-distance buffer
__device__ int    g_ccnt[M_ROWS];       // candidate counts (may exceed CAP)
__device__ int    g_cand[M_ROWS * CAP]; // candidate indices
__device__ int    g_idx[M_ROWS];
__device__ int    g_counts[NE];
__device__ double g_loss;

// TF32 rounding (approximation pass only)
__device__ __forceinline__ float tf32r(float x) {
    uint32_t u;
    asm("cvt.rna.tf32.f32 %0, %1;" : "=r"(u) : "f"(x));
    return __uint_as_float(u);
}

// m16n8k8 TF32 tensor-core MMA, fp32 accumulate
__device__ __forceinline__ void mma_tf32(float* c,
                                         const uint32_t* a,
                                         const uint32_t* b) {
    asm volatile(
        "mma.sync.aligned.m16n8k8.row.col.f32.tf32.tf32.f32 "
        "{%0,%1,%2,%3}, {%4,%5,%6,%7}, {%8,%9}, {%0,%1,%2,%3};"
        : "+f"(c[0]), "+f"(c[1]), "+f"(c[2]), "+f"(c[3])
        : "r"(a[0]), "r"(a[1]), "r"(a[2]), "r"(a[3]),
          "r"(b[0]), "r"(b[1]));
}

// ============================================================
// Row sum-of-squares. FROZEN: these exact bit patterns passed
// (zz participates in the reference's tie bucketing).
// ============================================================
__device__ __forceinline__ float row_sumsq(float x0, float x1,
                                           float* ws, int tid) {
    float v = __fadd_rn(__fmul_rn(x0, x0), __fmul_rn(x1, x1));
    #pragma unroll
    for (int o = 16; o >= 1; o >>= 1)
        v = __fadd_rn(v, __shfl_down_sync(0xffffffffu, v, o));
    if ((tid & 31) == 0) ws[tid >> 5] = v;
    __syncthreads();
    float r = 0.f;
    if (tid < 32) {
        float p = (tid < 8) ? ws[tid] : 0.f;
        #pragma unroll
        for (int o = 16; o >= 1; o >>= 1)
            p = __fadd_rn(p, __shfl_down_sync(0xffffffffu, p, o));
        r = p;
    }
    return r;
}

__global__ void see_kernel(const float* __restrict__ emb) {
    __shared__ float ws[8];
    const int j = blockIdx.x, tid = threadIdx.x;
    float2 x = *(const float2*)(emb + (size_t)j * EDIM + 2 * tid);
    float r = row_sumsq(x.x, x.y, ws, tid);
    if (tid == 0) {
        g_see[j]    = r;
        g_counts[j] = 0;
    }
}

__global__ void zz_kernel(const float* __restrict__ z) {
    __shared__ float ws[8];
    const int m = blockIdx.x, tid = threadIdx.x;
    const int n = m >> 9, t = m & 511;
    const float* base = z + (size_t)n * (EDIM * TDIM) + t;
    float x0 = base[(size_t)(2 * tid)     * TDIM];
    float x1 = base[(size_t)(2 * tid + 1) * TDIM];
    float r = row_sumsq(x0, x1, ws, tid);
    if (tid == 0) g_zz[m] = r;
}

// tiny init kernel (idempotent; also used to pad launch count so
// ncu -s 5 -c 1 captures the sweep as launch #6)
__global__ void init_kernel() {
    if (threadIdx.x == 0) g_loss = 0.0;
}

// ============================================================
// Kernel: TF32 tensor GEMM sweep (single pass). Computes
//   d_hat = fl( see[j] - fl(acc+acc) )     (zz omitted: row-constant)
// and stores fp16(d_hat) to g_dhat[m][j]. All later threshold logic
// operates on these stored values -> self-consistent by construction.
// Block tile 128x128, BK=32, 8 warps (4M x 2N), warp 32x64.
// grid = (2 code halves, 128 row tiles)
// ============================================================
#define BK 32
#define AS_STRIDE 136
#define BS_STRIDE 36

__global__ __launch_bounds__(256)
void sweep_kernel(const float* __restrict__ z,
                  const float* __restrict__ emb) {
    __shared__ float As[BK][AS_STRIDE];    // [k][m], tf32-rounded z
    __shared__ float Bs[128][BS_STRIDE];   // [j][k], tf32-rounded emb

    const int tid = threadIdx.x;
    const int h   = blockIdx.x;            // code half 0/1
    const int m0  = blockIdx.y * 128;      // row tile base
    const int nb  = m0 >> 9, t0 = m0 & 511;
    const float* zbase = z + (size_t)nb * EDIM * TDIM + t0;

    const int warpId = tid >> 5, lane = tid & 31;
    const int warpRow = warpId >> 1, warpCol = warpId & 1;
    const int wm = warpRow * 32, wn = warpCol * 64;
    const int r  = lane >> 2,  tg = lane & 3;

    const int jh0 = h * (NE / 2);

    for (int jt = 0; jt < 32; ++jt) {
        const int j0 = jh0 + jt * 128;
        float acc[2][8][4];
        #pragma unroll
        for (int am = 0; am < 2; am++)
            #pragma unroll
            for (int an = 0; an < 8; an++)
                #pragma unroll
                for (int q = 0; q < 4; q++) acc[am][an][q] = 0.f;

        for (int kt = 0; kt < 16; ++kt) {
            const int e0 = kt * BK;
            #pragma unroll
            for (int it = 0; it < 4; ++it) {
                int id = tid + it * 256;
                int k  = id >> 5, f4 = id & 31;
                float4 v = *(const float4*)(zbase + (size_t)(e0 + k) * TDIM + f4 * 4);
                v.x = tf32r(v.x); v.y = tf32r(v.y);
                v.z = tf32r(v.z); v.w = tf32r(v.w);
                *(float4*)&As[k][f4 * 4] = v;
            }
            #pragma unroll
            for (int it = 0; it < 4; ++it) {
                int id = tid + it * 256;
                int j  = id >> 3, q4 = id & 7;
                float4 v = *(const float4*)(emb + (size_t)(j0 + j) * EDIM + e0 + q4 * 4);
                v.x = tf32r(v.x); v.y = tf32r(v.y);
                v.z = tf32r(v.z); v.w = tf32r(v.w);
                *(float4*)&Bs[j][q4 * 4] = v;
            }
            __syncthreads();

            #pragma unroll
            for (int ks = 0; ks < 4; ++ks) {
                const int k8 = ks * 8;
                uint32_t a[2][4], b[8][2];
                #pragma unroll
                for (int am = 0; am < 2; ++am) {
                    int mb = wm + am * 16 + r;
                    a[am][0] = __float_as_uint(As[k8 + tg    ][mb]);
                    a[am][1] = __float_as_uint(As[k8 + tg    ][mb + 8]);
                    a[am][2] = __float_as_uint(As[k8 + tg + 4][mb]);
                    a[am][3] = __float_as_uint(As[k8 + tg + 4][mb + 8]);
                }
                #pragma unroll
                for (int an = 0; an < 8; ++an) {
                    int nf = wn + an * 8 + r;
                    b[an][0] = __float_as_uint(Bs[nf][k8 + tg]);
                    b[an][1] = __float_as_uint(Bs[nf][k8 + tg + 4]);
                }
                #pragma unroll
                for (int am = 0; am < 2; ++am)
                    #pragma unroll
                    for (int an = 0; an < 8; ++an)
                        mma_tf32(acc[am][an], a[am], b[an]);
            }
            __syncthreads();
        }

        // epilogue: d_hat -> fp16 pair store (j, j+1 adjacent)
        #pragma unroll
        for (int an = 0; an < 8; ++an) {
            int nloc = wn + an * 8 + tg * 2;
            int j = j0 + nloc;
            float s0 = __ldg(&g_see[j]);
            float s1 = __ldg(&g_see[j + 1]);
            #pragma unroll
            for (int am = 0; am < 2; ++am) {
                #pragma unroll
                for (int half = 0; half < 2; ++half) {
                    int row = m0 + wm + am * 16 + half * 8 + r;
                    float g0 = acc[am][an][half * 2 + 0];
                    float g1 = acc[am][an][half * 2 + 1];
                    float d0 = __fsub_rn(s0, __fadd_rn(g0, g0));
                    float d1 = __fsub_rn(s1, __fadd_rn(g1, g1));
                    __half2 hh = __floats2half2_rn(d0, d1);
                    *(__half2*)(&g_dhat[(size_t)row * NE + j]) = hh;
                }
            }
        }
    }
}

// ============================================================
// Kernel: per-row min + candidate collection from stored d_hat.
// One 256-thread block per row; coalesced __half2 reads.
// ============================================================
__global__ void cand_kernel() {
    __shared__ float ws[8];
    __shared__ float s_thr;
    __shared__ int   s_cnt;
    const int m = blockIdx.x, tid = threadIdx.x;
    const __half2* row = (const __half2*)(g_dhat + (size_t)m * NE);

    // load this thread's 16 half2 (coalesced: q = tid + p*256)
    __half2 v[16];
    #pragma unroll
    for (int p = 0; p < 16; ++p) v[p] = row[tid + p * 256];

    float lmin = 3.4e38f;
    #pragma unroll
    for (int p = 0; p < 16; ++p) {
        float2 f = __half22float2(v[p]);
        lmin = fminf(lmin, fminf(f.x, f.y));
    }
    #pragma unroll
    for (int o = 16; o >= 1; o >>= 1)
        lmin = fminf(lmin, __shfl_xor_sync(0xffffffffu, lmin, o));
    if ((tid & 31) == 0) ws[tid >> 5] = lmin;
    __syncthreads();
    if (tid == 0) {
        float mn = ws[0];
        #pragma unroll
        for (int q = 1; q < 8; q++) mn = fminf(mn, ws[q]);
        s_thr = mn + MARGIN;
        s_cnt = 0;
    }
    __syncthreads();

    const float thr = s_thr;
    #pragma unroll
    for (int p = 0; p < 16; ++p) {
        float2 f = __half22float2(v[p]);
        int jbase = (tid + p * 256) * 2;
        if (f.x <= thr) {
            int pos = atomicAdd(&s_cnt, 1);
            if (pos < CAP) g_cand[m * CAP + pos] = jbase;
        }
        if (f.y <= thr) {
            int pos = atomicAdd(&s_cnt, 1);
            if (pos < CAP) g_cand[m * CAP + pos] = jbase + 1;
        }
    }
    __syncthreads();
    if (tid == 0) g_ccnt[m] = s_cnt;
}

// ============================================================
// Kernel: exact resolution. One warp per row; reference-exact serial
// ascending-K fp32 FMA chain + epilogue d = fl(fl(zz+see)-fl(g+g));
// lexicographic (d, idx) min. Fallback: exact full scan if cnt > CAP.
// ============================================================
__global__ void resolve_kernel(const float* __restrict__ z,
                               const float* __restrict__ emb) {
    const int tid = threadIdx.x;
    const int lane = tid & 31;
    const int m = blockIdx.x * 8 + (tid >> 5);
    const int n = m >> 9, t = m & 511;
    const float* zrow = z + (size_t)n * (EDIM * TDIM) + t;
    const float zz = __ldg(&g_zz[m]);
    const int cnt = g_ccnt[m];

    float bv = 3.4e38f;
    int   bi = 0x7fffffff;

    if (cnt <= CAP) {
        if (lane < cnt) {
            int j = g_cand[m * CAP + lane];
            const float* e = emb + (size_t)j * EDIM;
            float acc = 0.f;
            #pragma unroll 8
            for (int k = 0; k < EDIM; ++k)
                acc = __fmaf_rn(zrow[(size_t)k * TDIM], __ldg(&e[k]), acc);
            bv = __fsub_rn(__fadd_rn(zz, __ldg(&g_see[j])),
                           __fadd_rn(acc, acc));
            bi = j;
        }
    } else {
        // sound fallback: exact scan of every code
        for (int j = lane; j < NE; j += 32) {
            const float* e = emb + (size_t)j * EDIM;
            float acc = 0.f;
            #pragma unroll 8
            for (int k = 0; k < EDIM; ++k)
                acc = __fmaf_rn(zrow[(size_t)k * TDIM], __ldg(&e[k]), acc);
            float d = __fsub_rn(__fadd_rn(zz, __ldg(&g_see[j])),
                                __fadd_rn(acc, acc));
            if (d < bv || (d == bv && j < bi)) { bv = d; bi = j; }
        }
    }

    #pragma unroll
    for (int o = 16; o >= 1; o >>= 1) {
        float ov = __shfl_down_sync(0xffffffffu, bv, o);
        int   oi = __shfl_down_sync(0xffffffffu, bi, o);
        if (ov < bv || (ov == bv && oi < bi)) { bv = ov; bi = oi; }
    }
    if (lane == 0) {
        g_idx[m] = bi;
        atomicAdd(&g_counts[bi], 1);
    }
}

// ============================================================
// Kernel: straight-through output (reference's exact two rounding
// ops -> bitwise output with matching idx) + fp64 loss accumulation
// ============================================================
__global__ void output_loss_kernel(const float* __restrict__ z,
                                   const float* __restrict__ emb,
                                   float* __restrict__ out) {
    int g = blockIdx.x * blockDim.x + threadIdx.x;   // < NET exactly
    int t = g & (TDIM - 1);
    int e = (g >> 9) & (EDIM - 1);
    int n = g >> 18;
    int m = n * TDIM + t;
    int j = g_idx[m];
    float zf = z[g];
    float zq = __ldg(emb + (size_t)j * EDIM + e);
    float dsub = __fsub_rn(zq, zf);      // fl(z_q - zf)
    out[g] = __fadd_rn(zf, dsub);        // fl(zf + fl(z_q - zf))
    float sq = __fmul_rn(dsub, dsub);

    __shared__ float red[256];
    red[threadIdx.x] = sq;
    __syncthreads();
    #pragma unroll
    for (int s = 128; s > 0; s >>= 1) {
        if (threadIdx.x < s) red[threadIdx.x] += red[threadIdx.x + s];
        __syncthreads();
    }
    if (threadIdx.x == 0) atomicAdd(&g_loss, (double)red[0]);
}

// ============================================================
// Kernel: perplexity + scalars
// ============================================================
__global__ void scalar_kernel(float* __restrict__ out) {
    __shared__ double red[256];
    double s = 0.0;
    for (int j = threadIdx.x; j < NE; j += 256) {
        float em   = (float)g_counts[j] / (float)M_ROWS;
        float term = em * logf(em + 1e-10f);
        s += (double)term;
    }
    red[threadIdx.x] = s;
    __syncthreads();
    #pragma unroll
    for (int st = 128; st > 0; st >>= 1) {
        if (threadIdx.x < st) red[threadIdx.x] += red[threadIdx.x + st];
        __syncthreads();
    }
    if (threadIdx.x == 0) {
        double mean = g_loss / (double)((size_t)M_ROWS * EDIM);
        out[NET]     = (float)(1.25 * mean);       // (1 + BETA) * mean
        out[NET + 1] = expf((float)(-red[0]));     // perplexity
    }
}

// ============================================================
extern "C" void kernel_launch(void* const* d_in, const int* in_sizes, int n_in,
                              void* d_out, int out_size) {
    (void)in_sizes; (void)n_in; (void)out_size;
    const float* z   = (const float*)d_in[0];   // [N, E, T] fp32
    const float* emb = (const float*)d_in[1];   // [n_e, E] fp32
    float* out = (float*)d_out;

    see_kernel<<<NE, 256>>>(emb);               // 1
    zz_kernel<<<M_ROWS, 256>>>(z);              // 2
    init_kernel<<<1, 32>>>();                   // 3 (pad for ncu -s 5)
    init_kernel<<<1, 32>>>();                   // 4 (pad)
    init_kernel<<<1, 32>>>();                   // 5 (pad)

    dim3 g2(2, 128);
    sweep_kernel<<<g2, 256>>>(z, emb);          // 6: the GEMM (ncu slot)

    cand_kernel<<<M_ROWS, 256>>>();             // 7
    resolve_kernel<<<M_ROWS / 8, 256>>>(z, emb);        // 8
    output_loss_kernel<<<NET / 256, 256>>>(z, emb, out); // 9
    scalar_kernel<<<1, 256>>>(out);             // 10
}